// round 3
// baseline (speedup 1.0000x reference)
#include <cuda_runtime.h>
#include <math.h>

#define BB   32
#define TT   512
#define CC   4233
#define UU   64
#define LABT 129
#define PADV (-3.4028234663852886e38f)   // jnp.finfo(float32).min
#define FULL 0xffffffffu
#define PD   6                            // prefetch distance (steps)

// scratch: Viterbi path indices per (b,t)
__device__ unsigned short g_wi[BB * TT];

// ---------------------------------------------------------------------------
// 2-term LSE: val = e + m + log(1 + exp(min-m));  d = argmax([a0, a1]) offset
__device__ __forceinline__ float step2(float e, float a0, float a1, unsigned &d)
{
    float m  = fmaxf(a0, a1);
    float mn = fminf(a0, a1);
    float s  = 1.0f + expf(mn - m);
    d = (a1 > a0) ? 1u : 0u;
    return e + m + logf(s);
}

// 3-term LSE with cond (cond -> drop a2 term, matching reference)
__device__ __forceinline__ float step3(float e, float a0, float a1, float a2,
                                       bool cond, unsigned &d)
{
    float a2e = cond ? PADV : a2;
    float hi  = fmaxf(a0, a1);
    float lo  = fminf(a0, a1);
    float m   = fmaxf(hi, a2e);
    float sec = fminf(hi, fmaxf(lo, a2e));
    float thr = fminf(lo, a2e);
    float s   = 1.0f + expf(sec - m) + expf(thr - m);
    d = (a2e > hi) ? 2u : ((a1 > a0) ? 1u : 0u);
    return e + m + logf(s);
}

// ---------------------------------------------------------------------------
// One warp per batch. No barriers; recurrence via 1 shfl per step.
// ---------------------------------------------------------------------------
__global__ __launch_bounds__(32, 1)
void dp_kernel(const float* __restrict__ logit,
               const int*   __restrict__ label,
               const int*   __restrict__ blankp,
               unsigned short* __restrict__ wi_out,
               float* __restrict__ out_loss)
{
    __shared__ unsigned char  dsm[TT * 32];   // delta byte per (t, lane)
    __shared__ unsigned       d128[TT / 32];  // 1-bit deltas for j=128
    __shared__ unsigned short wi_sm[TT];

    const int lane  = threadIdx.x;
    const int b     = blockIdx.x;
    const int blank = blankp ? *blankp : 0;

    // lane owns j = 4*lane + r, r=0..3; lane 31 also owns j=128 (slot 4).
    // odd slots carry labels u = 2*lane (j=4l+1) and u = 2*lane+1 (j=4l+3).
    const int lab1 = label[(2 * lane)     * BB + b];
    const int lab3 = label[(2 * lane + 1) * BB + b];
    const int ej1  = (lab1 == blank) ? -1 : lab1;
    const int ej3  = (lab3 == blank) ? -1 : lab3;
    int pej3 = __shfl_up_sync(FULL, ej3, 1);
    if (lane == 0) pej3 = -1;
    const bool cond1 = (ej1 == blank) || (ej1 == pej3);
    const bool cond3 = (ej3 == blank) || (ej3 == ej1);

    // column indices (negative-wrap like jnp: -1 % C -> C-1)
    const int cb = ((blank % CC) + CC) % CC;
    const int c1 = (ej1 < 0) ? (CC - 1) : (ej1 % CC);
    const int c3 = (ej3 < 0) ? (CC - 1) : (ej3 % CC);

    const float* __restrict__ pbase = logit + (size_t)b * TT * CC;

    // prefetch buffers (slot = t % PD)
    float ebB[PD], e1B[PD], e3B[PD];
    #pragma unroll
    for (int tp = 0; tp < PD; tp++) {
        const float* row = pbase + (size_t)tp * CC;
        ebB[tp] = row[cb]; e1B[tp] = row[c1]; e3B[tp] = row[c3];
    }

    float v0, v1, v2, v3, v4;
    unsigned d128acc = 0;

    // ---- t = 0 init ----
    v0 = (lane == 0) ? ebB[0] : PADV;   // dp0[0] = emit[0][0]
    v1 = (lane == 0) ? e1B[0] : PADV;   // dp0[1] = emit[0][1]
    v2 = PADV; v3 = PADV; v4 = PADV;
    { // refill slot 0 with t = PD
        const float* row = pbase + (size_t)PD * CC;
        ebB[0] = row[cb]; e1B[0] = row[c1]; e3B[0] = row[c3];
    }

    // ---- main recurrence, t = 1..511 ----
    for (int tb = 0; tb < TT; tb += PD) {
        #pragma unroll
        for (int k = 0; k < PD; k++) {
            const int t = tb + k;
            if (t < 1 || t >= TT) continue;
            const float eb = ebB[k], ee1 = e1B[k], ee3 = e3B[k];
            // prefetch t+PD into slot k
            if (t + PD < TT) {
                const float* row = pbase + (size_t)(t + PD) * CC;
                ebB[k] = row[cb]; e1B[k] = row[c1]; e3B[k] = row[c3];
            }
            float pv3 = __shfl_up_sync(FULL, v3, 1);  // dp_prev[4l-1]
            if (lane == 0) pv3 = PADV;

            unsigned d0, d1, d2, d3, d4;
            const float n0 = step2(eb,  v0, pv3, d0);            // j=4l   (even)
            const float n1 = step3(ee1, v1, v0, pv3, cond1, d1); // j=4l+1
            const float n2 = step2(eb,  v2, v1, d2);             // j=4l+2 (even)
            const float n3 = step3(ee3, v3, v2, v1, cond3, d3);  // j=4l+3
            const float n4 = step2(eb,  v4, v3, d4);             // j=128  (lane31)

            v0 = n0; v1 = n1; v2 = n2; v3 = n3; v4 = n4;

            dsm[t * 32 + lane] =
                (unsigned char)(d0 | (d1 << 2) | (d2 << 4) | (d3 << 6));
            d128acc |= (d4 & 1u) << (t & 31);
            if ((t & 31) == 31) {
                if (lane == 31) d128[t >> 5] = d128acc;
                d128acc = 0;
            }
        }
    }
    __syncwarp();

    // ---- yl, terminal values ----
    const unsigned m1 = __ballot_sync(FULL, lab1 != blank);
    const unsigned m3 = __ballot_sync(FULL, lab3 != blank);
    const int yl = 2 * (__popc(m1) + __popc(m3)) + 1;

    // fetch dp_last[idx] across lanes (idx uniform)
    auto fetch = [&](int idx) -> float {
        if (idx == 128) return __shfl_sync(FULL, v4, 31);
        const int r = idx & 3;
        float sv = (r == 0) ? v0 : (r == 1) ? v1 : (r == 2) ? v2 : v3;
        return __shfl_sync(FULL, sv, idx >> 2);
    };
    const float dv1 = fetch(yl - 1);
    const float dv2 = fetch(yl - 2);

    if (lane == 0) {
        int wi = (dv1 > dv2) ? (yl - 1) : (yl - 2);
        for (int t = TT - 1; t >= 1; t--) {
            wi_sm[t] = (unsigned short)wi;
            int d;
            if (wi == 128) d = (int)((d128[t >> 5] >> (t & 31)) & 1u);
            else {
                const unsigned byte = dsm[t * 32 + (wi >> 2)];
                d = (int)((byte >> ((wi & 3) * 2)) & 3u);
            }
            wi -= d;
        }
        wi_sm[0] = (unsigned short)wi;

        const float mm  = fmaxf(dv1, dv2);
        const float lse = mm + log1pf(expf(-fabsf(dv1 - dv2)));
        if (out_loss) out_loss[b] = -2.0f * lse / (float)(yl - 1);
    }
    __syncwarp();

    // publish path for the align kernel (coalesced)
    for (int t = lane; t < TT; t += 32)
        wi_out[b * TT + t] = wi_sm[t];
}

// ---------------------------------------------------------------------------
// Full-chip one-hot alignment write (8.45 MB, write-bound)
// ---------------------------------------------------------------------------
__global__ void align_kernel(const unsigned short* __restrict__ wi,
                             float* __restrict__ out)
{
    const unsigned idx = blockIdx.x * blockDim.x + threadIdx.x;
    const unsigned total = (unsigned)BB * TT * LABT;
    if (idx >= total) return;
    const unsigned j  = idx % LABT;
    const unsigned bt = idx / LABT;
    out[idx] = (j == (unsigned)wi[bt]) ? 1.0f : 0.0f;
}

// ---------------------------------------------------------------------------
extern "C" void kernel_launch(void* const* d_in, const int* in_sizes, int n_in,
                              void* d_out, int out_size)
{
    const float* logit  = (const float*)d_in[0];
    const int*   label  = (const int*)d_in[1];
    const int*   blankp = (n_in >= 3) ? (const int*)d_in[2] : nullptr;

    float* out = (float*)d_out;
    const size_t align_elems = (size_t)BB * TT * LABT;   // 2,113,536
    float* out_loss = ((size_t)out_size >= align_elems + BB) ? (out + align_elems)
                                                             : nullptr;

    unsigned short* wi;
    cudaGetSymbolAddress((void**)&wi, g_wi);

    dp_kernel<<<BB, 32>>>(logit, label, blankp, wi, out_loss);
    const int total = BB * TT * LABT;
    align_kernel<<<(total + 255) / 256, 256>>>(wi, out);
}

// round 4
// speedup vs baseline: 1.6210x; 1.6210x over previous
#include <cuda_runtime.h>
#include <math.h>

#define BB   32
#define TT   512
#define CC   4233
#define UU   64
#define LABT 129
#define ROWP 132                          // padded row (16B-aligned)
#define PADV (-3.4028234663852886e38f)   // jnp.finfo(float32).min
#define FULL 0xffffffffu
#define PD   6                            // prefetch distance (steps)

// compact gathered emissions: [B][T][ROWP], 16B-aligned rows (L2-resident)
__device__ __align__(16) float g_emit[(size_t)BB * TT * ROWP];
// scratch: Viterbi path indices per (b,t)
__device__ unsigned short g_wi[BB * TT];

// ---------------------------------------------------------------------------
// Phase 1: gather emit[b,t,j] = logit[b,t, ext_idx[b,j]]  (full-chip, HBM)
// ---------------------------------------------------------------------------
__global__ void gather_kernel(const float* __restrict__ logit,
                              const int*   __restrict__ label,
                              const int*   __restrict__ blankp)
{
    const int blank = blankp ? *blankp : 0;
    unsigned idx = blockIdx.x * blockDim.x + threadIdx.x;
    const unsigned total = (unsigned)BB * TT * LABT;
    if (idx >= total) return;

    unsigned j  = idx % LABT;
    unsigned bt = idx / LABT;          // b*T + t  (T=512 -> b = bt>>9)

    int c;
    if (j & 1) {
        int l = label[(j >> 1) * BB + (bt >> 9)];
        if (l == blank) l = -1;        // pad sentinel, wraps like jnp % C
        c = l % CC; if (c < 0) c += CC;
    } else {
        c = blank % CC; if (c < 0) c += CC;
    }
    g_emit[(size_t)bt * ROWP + j] = logit[(size_t)bt * CC + (unsigned)c];
}

// ---------------------------------------------------------------------------
// 2-term LSE: val = e + m + log(1 + exp(min-m));  d = argmax offset
__device__ __forceinline__ float step2(float e, float a0, float a1, unsigned &d)
{
    float m  = fmaxf(a0, a1);
    float mn = fminf(a0, a1);
    float s  = 1.0f + expf(mn - m);
    d = (a1 > a0) ? 1u : 0u;
    return e + m + logf(s);
}

// 3-term LSE with cond (cond -> drop a2 term, matching reference)
__device__ __forceinline__ float step3(float e, float a0, float a1, float a2,
                                       bool cond, unsigned &d)
{
    float a2e = cond ? PADV : a2;
    float hi  = fmaxf(a0, a1);
    float lo  = fminf(a0, a1);
    float m   = fmaxf(hi, a2e);
    float sec = fminf(hi, fmaxf(lo, a2e));
    float thr = fminf(lo, a2e);
    float s   = 1.0f + expf(sec - m) + expf(thr - m);
    d = (a2e > hi) ? 2u : ((a1 > a0) ? 1u : 0u);
    return e + m + logf(s);
}

// ---------------------------------------------------------------------------
// Phase 2: one warp per batch, barrier-free; emissions from compact g_emit.
// Lane l owns j = 4l..4l+3 (lane 31 also j=128). One shfl per step.
// ---------------------------------------------------------------------------
__global__ __launch_bounds__(32, 1)
void dp_kernel(const int* __restrict__ label,
               const int* __restrict__ blankp,
               unsigned short* __restrict__ wi_out,
               float* __restrict__ out_loss)
{
    __shared__ unsigned char  dsm[TT * 32];   // delta byte per (t, lane)
    __shared__ unsigned       d128[TT / 32];  // 1-bit deltas for j=128
    __shared__ unsigned short wi_sm[TT];

    const int lane  = threadIdx.x;
    const int b     = blockIdx.x;
    const int blank = blankp ? *blankp : 0;

    // cond flags for odd positions owned by this lane
    const int lab1 = label[(2 * lane)     * BB + b];
    const int lab3 = label[(2 * lane + 1) * BB + b];
    const int ej1  = (lab1 == blank) ? -1 : lab1;
    const int ej3  = (lab3 == blank) ? -1 : lab3;
    int pej3 = __shfl_up_sync(FULL, ej3, 1);
    if (lane == 0) pej3 = -1;
    const bool cond1 = (ej1 == blank) || (ej1 == pej3);
    const bool cond3 = (ej3 == blank) || (ej3 == ej1);

    const float4* __restrict__ erow =
        (const float4*)(g_emit + (size_t)b * TT * ROWP) + lane;   // lane's quad
    const float*  __restrict__ e128p =
        g_emit + (size_t)b * TT * ROWP + 128;
    const int q = ROWP / 4;                                       // quads/row

    // prefetch pipeline (slot = t % PD)
    float4 eB[PD];
    float  e4B[PD];
    #pragma unroll
    for (int tp = 0; tp < PD; tp++) {
        eB[tp]  = erow[tp * q];
        e4B[tp] = (lane == 31) ? e128p[(size_t)tp * ROWP] : PADV;
    }

    float v0, v1, v2, v3, v4;
    unsigned d128acc = 0;

    // ---- t = 0 init ----
    v0 = (lane == 0) ? eB[0].x : PADV;   // dp0[0]
    v1 = (lane == 0) ? eB[0].y : PADV;   // dp0[1]
    v2 = PADV; v3 = PADV; v4 = PADV;
    eB[0]  = erow[PD * q];               // refill slot 0 with t = PD
    e4B[0] = (lane == 31) ? e128p[(size_t)PD * ROWP] : PADV;

    // ---- main recurrence, t = 1..511 ----
    for (int tb = 0; tb < TT; tb += PD) {
        #pragma unroll
        for (int k = 0; k < PD; k++) {
            const int t = tb + k;
            if (t < 1 || t >= TT) continue;
            const float4 e  = eB[k];
            const float  eb = e.x;       // blank emit (j even)
            const float  e4 = e4B[k];
            if (t + PD < TT) {           // prefetch t+PD into slot k
                eB[k]  = erow[(t + PD) * q];
                e4B[k] = (lane == 31) ? e128p[(size_t)(t + PD) * ROWP] : PADV;
            }
            float pv3 = __shfl_up_sync(FULL, v3, 1);  // dp_prev[4l-1]
            if (lane == 0) pv3 = PADV;

            unsigned d0, d1, d2, d3, d4;
            const float n0 = step2(eb,  v0, pv3, d0);            // j=4l
            const float n1 = step3(e.y, v1, v0, pv3, cond1, d1); // j=4l+1
            const float n2 = step2(e.z, v2, v1, d2);             // j=4l+2
            const float n3 = step3(e.w, v3, v2, v1, cond3, d3);  // j=4l+3
            const float n4 = step2(e4,  v4, v3, d4);             // j=128 (lane31)

            v0 = n0; v1 = n1; v2 = n2; v3 = n3; v4 = n4;

            dsm[t * 32 + lane] =
                (unsigned char)(d0 | (d1 << 2) | (d2 << 4) | (d3 << 6));
            d128acc |= (d4 & 1u) << (t & 31);
            if ((t & 31) == 31) {
                if (lane == 31) d128[t >> 5] = d128acc;
                d128acc = 0;
            }
        }
    }
    __syncwarp();

    // ---- yl, terminal values ----
    const unsigned m1 = __ballot_sync(FULL, lab1 != blank);
    const unsigned m3 = __ballot_sync(FULL, lab3 != blank);
    const int yl = 2 * (__popc(m1) + __popc(m3)) + 1;

    auto fetch = [&](int idx) -> float {
        if (idx == 128) return __shfl_sync(FULL, v4, 31);
        const int r = idx & 3;
        float sv = (r == 0) ? v0 : (r == 1) ? v1 : (r == 2) ? v2 : v3;
        return __shfl_sync(FULL, sv, idx >> 2);
    };
    const float dv1 = fetch(yl - 1);
    const float dv2 = fetch(yl - 2);

    if (lane == 0) {
        int wi = (dv1 > dv2) ? (yl - 1) : (yl - 2);
        for (int t = TT - 1; t >= 1; t--) {
            wi_sm[t] = (unsigned short)wi;
            int d;
            if (wi == 128) d = (int)((d128[t >> 5] >> (t & 31)) & 1u);
            else {
                const unsigned byte = dsm[t * 32 + (wi >> 2)];
                d = (int)((byte >> ((wi & 3) * 2)) & 3u);
            }
            wi -= d;
        }
        wi_sm[0] = (unsigned short)wi;

        const float mm  = fmaxf(dv1, dv2);
        const float lse = mm + log1pf(expf(-fabsf(dv1 - dv2)));
        if (out_loss) out_loss[b] = -2.0f * lse / (float)(yl - 1);
    }
    __syncwarp();

    for (int t = lane; t < TT; t += 32)
        wi_out[b * TT + t] = wi_sm[t];
}

// ---------------------------------------------------------------------------
// Full-chip one-hot alignment write, float4-vectorized (total % 4 == 0)
// ---------------------------------------------------------------------------
__global__ void align_kernel(const unsigned short* __restrict__ wi,
                             float4* __restrict__ out)
{
    const unsigned i = blockIdx.x * blockDim.x + threadIdx.x;
    const unsigned total4 = (unsigned)BB * TT * LABT / 4;
    if (i >= total4) return;
    unsigned idx = i * 4;
    unsigned j  = idx % LABT;
    unsigned bt = idx / LABT;
    float r[4];
    #pragma unroll
    for (int e = 0; e < 4; e++) {
        r[e] = (j == (unsigned)wi[bt]) ? 1.0f : 0.0f;
        if (++j == LABT) { j = 0; bt++; }
    }
    out[i] = make_float4(r[0], r[1], r[2], r[3]);
}

// ---------------------------------------------------------------------------
extern "C" void kernel_launch(void* const* d_in, const int* in_sizes, int n_in,
                              void* d_out, int out_size)
{
    const float* logit  = (const float*)d_in[0];
    const int*   label  = (const int*)d_in[1];
    const int*   blankp = (n_in >= 3) ? (const int*)d_in[2] : nullptr;

    float* out = (float*)d_out;
    const size_t align_elems = (size_t)BB * TT * LABT;   // 2,113,536
    float* out_loss = ((size_t)out_size >= align_elems + BB) ? (out + align_elems)
                                                             : nullptr;

    unsigned short* wi;
    cudaGetSymbolAddress((void**)&wi, g_wi);

    const int total = BB * TT * LABT;
    gather_kernel<<<(total + 255) / 256, 256>>>(logit, label, blankp);
    dp_kernel<<<BB, 32>>>(label, blankp, wi, out_loss);
    align_kernel<<<(total / 4 + 255) / 256, 256>>>(wi, (float4*)out);
}

// round 6
// speedup vs baseline: 2.4843x; 1.5326x over previous
#include <cuda_runtime.h>
#include <math.h>

#define BB   32
#define TT   512
#define CC   4233
#define UU   64
#define LABT 129
#define ROWP 132                          // padded row (16B-aligned)
#define PADV (-3.4028234663852886e38f)   // jnp.finfo(float32).min
#define FULL 0xffffffffu
#define PD   8                            // prefetch distance (divides TT)

// compact gathered emissions: [B][T][ROWP], 16B-aligned rows (L2-resident)
__device__ __align__(16) float g_emit[(size_t)BB * TT * ROWP];
// scratch: Viterbi path indices per (b,t)
__device__ unsigned short g_wi[BB * TT];

// ---------------------------------------------------------------------------
// Phase 1: gather emit[b,t,j] = logit[b,t, ext_idx[b,j]]  (full-chip, HBM)
// ---------------------------------------------------------------------------
__global__ void gather_kernel(const float* __restrict__ logit,
                              const int*   __restrict__ label,
                              const int*   __restrict__ blankp)
{
    const int blank = blankp ? *blankp : 0;
    unsigned idx = blockIdx.x * blockDim.x + threadIdx.x;
    const unsigned total = (unsigned)BB * TT * LABT;
    if (idx >= total) return;

    unsigned j  = idx % LABT;
    unsigned bt = idx / LABT;          // b*T + t  (T=512 -> b = bt>>9)

    int c;
    if (j & 1) {
        int l = label[(j >> 1) * BB + (bt >> 9)];
        if (l == blank) l = -1;        // pad sentinel, wraps like jnp % C
        c = l % CC; if (c < 0) c += CC;
    } else {
        c = blank % CC; if (c < 0) c += CC;
    }
    g_emit[(size_t)bt * ROWP + j] = logit[(size_t)bt * CC + (unsigned)c];
}

// ---------------------------------------------------------------------------
// fast LSE steps (branchless MUFU EX2/LG2)
__device__ __forceinline__ float step2f(float e, float a0, float a1, unsigned &d)
{
    float m  = fmaxf(a0, a1);
    float mn = fminf(a0, a1);
    float s  = 1.0f + __expf(mn - m);
    d = (a1 > a0) ? 1u : 0u;
    return e + m + __logf(s);
}

__device__ __forceinline__ float step3f(float e, float a0, float a1, float a2,
                                        bool cond, unsigned &d)
{
    float a2e = cond ? PADV : a2;
    float hi  = fmaxf(a0, a1);
    float lo  = fminf(a0, a1);
    float m   = fmaxf(hi, a2e);
    float sec = fminf(hi, fmaxf(lo, a2e));
    float thr = fminf(lo, a2e);
    float s   = 1.0f + __expf(sec - m) + __expf(thr - m);
    d = (a2e > hi) ? 2u : ((a1 > a0) ? 1u : 0u);
    return e + m + __logf(s);
}

// ---------------------------------------------------------------------------
// Phase 2: one warp per batch, barrier-free; emissions from compact g_emit.
// Lane l owns j = 4l..4l+3 (lane 31 also j=128). One pipelined shfl per step.
// ---------------------------------------------------------------------------
__global__ __launch_bounds__(32, 1)
void dp_kernel(const int* __restrict__ label,
               const int* __restrict__ blankp,
               unsigned short* __restrict__ wi_out,
               float* __restrict__ out_loss)
{
    __shared__ unsigned char  dsm[TT * 32];   // delta byte per (t, lane)
    __shared__ unsigned       d128[TT / 32];  // 1-bit deltas for j=128
    __shared__ unsigned short wi_sm[TT];

    const int lane  = threadIdx.x;
    const int b     = blockIdx.x;
    const int blank = blankp ? *blankp : 0;

    // cond flags for odd positions owned by this lane
    const int lab1 = label[(2 * lane)     * BB + b];
    const int lab3 = label[(2 * lane + 1) * BB + b];
    const int ej1  = (lab1 == blank) ? -1 : lab1;
    const int ej3  = (lab3 == blank) ? -1 : lab3;
    int pej3 = __shfl_up_sync(FULL, ej3, 1);
    if (lane == 0) pej3 = -1;
    const bool cond1 = (ej1 == blank) || (ej1 == pej3);
    const bool cond3 = (ej3 == blank) || (ej3 == ej1);

    const float4* __restrict__ erow =
        (const float4*)(g_emit + (size_t)b * TT * ROWP) + lane;   // lane's quad
    const float*  __restrict__ e128p =
        g_emit + (size_t)b * TT * ROWP + 128;
    const int q = ROWP / 4;                                       // quads/row
    const bool l31 = (lane == 31);

    float4 eB[PD];
    float  e4B[PD];
    #pragma unroll
    for (int tp = 0; tp < PD; tp++) {
        eB[tp]  = erow[tp * q];
        e4B[tp] = l31 ? e128p[(size_t)tp * ROWP] : PADV;
    }

    float v0, v1, v2, v3, v4, pv3;
    unsigned d128acc = 0;

    // ---- t = 0 init ----
    v0 = (lane == 0) ? eB[0].x : PADV;
    v1 = (lane == 0) ? eB[0].y : PADV;
    v2 = PADV; v3 = PADV; v4 = PADV; pv3 = PADV;
    eB[0]  = erow[PD * q];                   // refill slot 0 with t = PD
    e4B[0] = l31 ? e128p[(size_t)PD * ROWP] : PADV;

    auto STEP = [&](int t, int slot) {
        const float4 e  = eB[slot];
        const float  e4 = e4B[slot];
        if (t + PD < TT) {                   // prefetch t+PD into slot
            eB[slot]  = erow[(t + PD) * q];
            e4B[slot] = l31 ? e128p[(size_t)(t + PD) * ROWP] : PADV;
        }
        unsigned d0, d1, d2, d3, d4;
        const float n0 = step2f(e.x, v0, pv3, d0);            // j=4l
        const float n1 = step3f(e.y, v1, v0, pv3, cond1, d1); // j=4l+1
        const float n2 = step2f(e.z, v2, v1, d2);             // j=4l+2
        const float n3 = step3f(e.w, v3, v2, v1, cond3, d3);  // j=4l+3
        const float n4 = step2f(e4,  v4, v3, d4);             // j=128 (lane31)
        v0 = n0; v1 = n1; v2 = n2; v3 = n3; v4 = n4;
        pv3 = __shfl_up_sync(FULL, v3, 1);                    // for step t+1
        if (lane == 0) pv3 = PADV;
        dsm[t * 32 + lane] =
            (unsigned char)(d0 | (d1 << 2) | (d2 << 4) | (d3 << 6));
        d128acc |= (d4 & 1u) << (t & 31);
        if ((t & 31) == 31) {
            if (l31) d128[t >> 5] = d128acc;
            d128acc = 0;
        }
    };

    // peeled first block: t = 1..PD-1
    #pragma unroll
    for (int k = 1; k < PD; k++) STEP(k, k);
    // main blocks: t = PD..TT-1
    for (int tb = PD; tb < TT; tb += PD) {
        #pragma unroll
        for (int k = 0; k < PD; k++) STEP(tb + k, k);
    }
    __syncwarp();

    // ---- yl, terminal values ----
    const unsigned m1 = __ballot_sync(FULL, lab1 != blank);
    const unsigned m3 = __ballot_sync(FULL, lab3 != blank);
    const int yl = 2 * (__popc(m1) + __popc(m3)) + 1;

    auto fetch = [&](int idx) -> float {
        if (idx == 128) return __shfl_sync(FULL, v4, 31);
        const int r = idx & 3;
        float sv = (r == 0) ? v0 : (r == 1) ? v1 : (r == 2) ? v2 : v3;
        return __shfl_sync(FULL, sv, idx >> 2);
    };
    const float dv1 = fetch(yl - 1);
    const float dv2 = fetch(yl - 2);

    // ---- warp-cooperative speculative backtrack (wi is non-increasing) ----
    {
        int wi = (dv1 > dv2) ? (yl - 1) : (yl - 2);
        int t  = TT - 1;
        while (t >= 1) {
            const int tt = t - lane;
            const bool valid = (tt >= 1);
            int d = 0;
            if (valid) {
                if (wi == 128) d = (int)((d128[tt >> 5] >> (tt & 31)) & 1u);
                else {
                    const unsigned byte = dsm[tt * 32 + (wi >> 2)];
                    d = (int)((byte >> ((wi & 3) * 2)) & 3u);
                }
            }
            const unsigned nz = __ballot_sync(FULL, valid && (d != 0));
            const int nvalid = (t < 32) ? t : 32;
            const int first  = nz ? (__ffs(nz) - 1) : 32;
            const int adv    = (first + 1 < nvalid) ? (first + 1) : nvalid;
            if (lane < adv) wi_sm[tt] = (unsigned short)wi;
            const int dfirst = __shfl_sync(FULL, d, (first < 31) ? first : 31);
            if (first < nvalid) wi -= dfirst;
            t -= adv;
        }
        if (lane == 0) {
            wi_sm[0] = (unsigned short)wi;
            const float mm  = fmaxf(dv1, dv2);
            const float lse = mm + log1pf(expf(-fabsf(dv1 - dv2)));
            if (out_loss) out_loss[b] = -2.0f * lse / (float)(yl - 1);
        }
    }
    __syncwarp();

    for (int t = lane; t < TT; t += 32)
        wi_out[b * TT + t] = wi_sm[t];
}

// ---------------------------------------------------------------------------
// One warp per (b,t) row: broadcast wi, contiguous one-hot stores
// ---------------------------------------------------------------------------
__global__ void align_kernel(const unsigned short* __restrict__ wi,
                             float* __restrict__ out)
{
    const int w    = (blockIdx.x * blockDim.x + threadIdx.x) >> 5;  // row = b*T+t
    const int lane = threadIdx.x & 31;
    if (w >= BB * TT) return;
    const int wiv = (int)wi[w];
    float* row = out + (size_t)w * LABT;
    #pragma unroll
    for (int j = lane; j < LABT; j += 32)
        row[j] = (j == wiv) ? 1.0f : 0.0f;
}

// ---------------------------------------------------------------------------
extern "C" void kernel_launch(void* const* d_in, const int* in_sizes, int n_in,
                              void* d_out, int out_size)
{
    const float* logit  = (const float*)d_in[0];
    const int*   label  = (const int*)d_in[1];
    const int*   blankp = (n_in >= 3) ? (const int*)d_in[2] : nullptr;

    float* out = (float*)d_out;
    const size_t align_elems = (size_t)BB * TT * LABT;   // 2,113,536
    float* out_loss = ((size_t)out_size >= align_elems + BB) ? (out + align_elems)
                                                             : nullptr;

    unsigned short* wi;
    cudaGetSymbolAddress((void**)&wi, g_wi);

    const int total = BB * TT * LABT;
    gather_kernel<<<(total + 255) / 256, 256>>>(logit, label, blankp);
    dp_kernel<<<BB, 32>>>(label, blankp, wi, out_loss);
    align_kernel<<<(BB * TT * 32 + 255) / 256, 256>>>(wi, out);
}

// round 7
// speedup vs baseline: 2.5570x; 1.0293x over previous
#include <cuda_runtime.h>
#include <math.h>

#define BB   32
#define TT   512
#define CC   4233
#define UU   64
#define LABT 129
#define ROWE 66                           // compact row: 64 odds + blank + pad
#define PADV (-3.4028234663852886e38f)   // jnp.finfo(float32).min
#define FULL 0xffffffffu
#define PD   8                            // prefetch distance (divides TT)

// compact gathered emissions: [B][T][ROWE]  (~4.3 MB, L2-resident)
__device__ __align__(16) float g_emit[(size_t)BB * TT * ROWE];
// scratch: Viterbi path indices per (b,t)
__device__ unsigned short g_wi[BB * TT];

// ---------------------------------------------------------------------------
// Phase 1: gather. Row layout: [0..63] = emit(label_u), [64] = emit(blank).
// ---------------------------------------------------------------------------
__global__ void gather_kernel(const float* __restrict__ logit,
                              const int*   __restrict__ label,
                              const int*   __restrict__ blankp)
{
    const int blank = blankp ? *blankp : 0;
    unsigned idx = blockIdx.x * blockDim.x + threadIdx.x;
    const unsigned total = (unsigned)BB * TT * 65;
    if (idx >= total) return;

    unsigned j  = idx % 65;            // 0..63 label slots, 64 = blank
    unsigned bt = idx / 65;            // b*T + t  (b = bt>>9)

    int c;
    if (j < 64) {
        int l = label[j * BB + (bt >> 9)];
        if (l == blank) l = -1;        // pad sentinel, wraps like jnp % C
        c = l % CC; if (c < 0) c += CC;
    } else {
        c = blank % CC; if (c < 0) c += CC;
    }
    g_emit[(size_t)bt * ROWE + j] = logit[(size_t)bt * CC + (unsigned)c];
}

// ---------------------------------------------------------------------------
// fast LSE steps (branchless MUFU EX2/LG2)
__device__ __forceinline__ float step2f(float e, float a0, float a1, unsigned &d)
{
    float m  = fmaxf(a0, a1);
    float mn = fminf(a0, a1);
    float s  = 1.0f + __expf(mn - m);
    d = (a1 > a0) ? 1u : 0u;
    return e + m + __logf(s);
}

__device__ __forceinline__ float step3f(float e, float a0, float a1, float a2,
                                        bool cond, unsigned &d)
{
    float a2e = cond ? PADV : a2;
    float hi  = fmaxf(a0, a1);
    float lo  = fminf(a0, a1);
    float m   = fmaxf(hi, a2e);
    float sec = fminf(hi, fmaxf(lo, a2e));
    float thr = fminf(lo, a2e);
    float s   = 1.0f + __expf(sec - m) + __expf(thr - m);
    d = (a2e > hi) ? 2u : ((a1 > a0) ? 1u : 0u);
    return e + m + __logf(s);
}

// ---------------------------------------------------------------------------
// Phase 2: one warp per batch, barrier-free.
// j=0 is a free running sum z. Lane l owns j = 4l+1 .. 4l+4.
// Boundary values pv3 = dp[4l-1], pv4 = dp[4l] via two pipelined shfls.
// ---------------------------------------------------------------------------
__global__ __launch_bounds__(32, 1)
void dp_kernel(const int* __restrict__ label,
               const int* __restrict__ blankp,
               unsigned short* __restrict__ wi_out,
               float* __restrict__ out_loss)
{
    __shared__ unsigned char  dsm[TT * 32];   // delta byte per (t, lane)
    __shared__ unsigned short wi_sm[TT];

    const int lane  = threadIdx.x;
    const int b     = blockIdx.x;
    const int blank = blankp ? *blankp : 0;

    // labels owned by this lane: u=2l (j=4l+1), u=2l+1 (j=4l+3)
    const int lab1 = label[(2 * lane)     * BB + b];
    const int lab3 = label[(2 * lane + 1) * BB + b];
    const int ej1  = (lab1 == blank) ? -1 : lab1;
    const int ej3  = (lab3 == blank) ? -1 : lab3;
    int pej3 = __shfl_up_sync(FULL, ej3, 1);
    if (lane == 0) pej3 = -1;                    // ext[-1] pad
    const bool cond1 = (ej1 == blank) || (ej1 == pej3);
    const bool cond3 = (ej3 == blank) || (ej3 == ej1);

    const float*  __restrict__ rowb = g_emit + (size_t)b * TT * ROWE;
    const float2* __restrict__ erow = (const float2*)rowb + lane;   // odds 2l,2l+1
    const float*  __restrict__ ebp  = rowb + 64;
    const int q2 = ROWE / 2;                                        // float2/row

    float2 eB[PD];
    float  ebB[PD];
    #pragma unroll
    for (int tp = 0; tp < PD; tp++) {
        eB[tp]  = erow[tp * q2];
        ebB[tp] = ebp[(size_t)tp * ROWE];
    }

    // ---- t = 0 init ----
    float z  = ebB[0];                           // dp[0](0) = emit blank
    float v1 = (lane == 0) ? eB[0].x : PADV;     // dp[1](0) = emit(label_0)
    float v2 = PADV, v3 = PADV, v4 = PADV;
    float pv3 = PADV;
    float pv4 = (lane == 0) ? z : PADV;
    eB[0]  = erow[PD * q2];                      // refill slot 0 with t = PD
    ebB[0] = ebp[(size_t)PD * ROWE];

    auto STEP = [&](int t, int slot) {
        const float2 eo = eB[slot];
        const float  eb = ebB[slot];
        if (t + PD < TT) {
            eB[slot]  = erow[(t + PD) * q2];
            ebB[slot] = ebp[(size_t)(t + PD) * ROWE];
        }
        unsigned d1, d2, d3, d4;
        const float n1 = step3f(eo.x, v1, pv4, pv3, cond1, d1);  // j=4l+1
        const float n2 = step2f(eb,  v2, v1, d2);                // j=4l+2
        const float n3 = step3f(eo.y, v3, v2, v1, cond3, d3);    // j=4l+3
        const float n4 = step2f(eb,  v4, v3, d4);                // j=4l+4
        z += eb;                                                 // j=0 (exact)
        v1 = n1; v2 = n2; v3 = n3; v4 = n4;
        const float s3 = __shfl_up_sync(FULL, v3, 1);
        const float s4 = __shfl_up_sync(FULL, v4, 1);
        pv3 = (lane == 0) ? PADV : s3;
        pv4 = (lane == 0) ? z    : s4;
        dsm[t * 32 + lane] =
            (unsigned char)(d1 | (d2 << 2) | (d3 << 4) | (d4 << 6));
    };

    #pragma unroll
    for (int k = 1; k < PD; k++) STEP(k, k);     // t = 1..PD-1
    for (int tb = PD; tb < TT; tb += PD) {
        #pragma unroll
        for (int k = 0; k < PD; k++) STEP(tb + k, k);
    }
    __syncwarp();

    // ---- yl, terminal values ----
    const unsigned m1 = __ballot_sync(FULL, lab1 != blank);
    const unsigned m3 = __ballot_sync(FULL, lab3 != blank);
    const int yl = 2 * (__popc(m1) + __popc(m3)) + 1;

    auto fetch = [&](int idx) -> float {
        idx = ((idx % LABT) + LABT) % LABT;      // jnp negative-wrap safety
        if (idx == 0) return z;                  // uniform
        const int s = (idx - 1) & 3;
        float sv = (s == 0) ? v1 : (s == 1) ? v2 : (s == 2) ? v3 : v4;
        return __shfl_sync(FULL, sv, (idx - 1) >> 2);
    };
    const float dv1 = fetch(yl - 1);
    const float dv2 = fetch(yl - 2);

    // ---- warp-cooperative speculative backtrack (wi non-increasing) ----
    {
        int wi = (dv1 > dv2) ? (yl - 1) : (yl - 2);
        int t  = TT - 1;
        while (t >= 1) {
            const int tt = t - lane;
            const bool valid = (tt >= 1);
            int d = 0;
            if (valid && wi > 0) {
                const unsigned byte = dsm[tt * 32 + ((wi - 1) >> 2)];
                d = (int)((byte >> (((wi - 1) & 3) * 2)) & 3u);
            }
            const unsigned nz = __ballot_sync(FULL, valid && (d != 0));
            const int nvalid = (t < 32) ? t : 32;
            const int first  = nz ? (__ffs(nz) - 1) : 32;
            const int adv    = (first + 1 < nvalid) ? (first + 1) : nvalid;
            if (lane < adv) wi_sm[tt] = (unsigned short)wi;
            const int dfirst = __shfl_sync(FULL, d, (first < 31) ? first : 31);
            if (first < nvalid) wi -= dfirst;
            t -= adv;
        }
        if (lane == 0) {
            wi_sm[0] = (unsigned short)wi;
            const float mm  = fmaxf(dv1, dv2);
            const float lse = mm + log1pf(expf(-fabsf(dv1 - dv2)));
            if (out_loss) out_loss[b] = -2.0f * lse / (float)(yl - 1);
        }
    }
    __syncwarp();

    for (int t = lane; t < TT; t += 32)
        wi_out[b * TT + t] = wi_sm[t];
}

// ---------------------------------------------------------------------------
// One warp per (b,t) row: broadcast wi, contiguous one-hot stores
// ---------------------------------------------------------------------------
__global__ void align_kernel(const unsigned short* __restrict__ wi,
                             float* __restrict__ out)
{
    const int w    = (blockIdx.x * blockDim.x + threadIdx.x) >> 5;  // row = b*T+t
    const int lane = threadIdx.x & 31;
    if (w >= BB * TT) return;
    const int wiv = (int)wi[w];
    float* row = out + (size_t)w * LABT;
    #pragma unroll
    for (int j = lane; j < LABT; j += 32)
        row[j] = (j == wiv) ? 1.0f : 0.0f;
}

// ---------------------------------------------------------------------------
extern "C" void kernel_launch(void* const* d_in, const int* in_sizes, int n_in,
                              void* d_out, int out_size)
{
    const float* logit  = (const float*)d_in[0];
    const int*   label  = (const int*)d_in[1];
    const int*   blankp = (n_in >= 3) ? (const int*)d_in[2] : nullptr;

    float* out = (float*)d_out;
    const size_t align_elems = (size_t)BB * TT * LABT;   // 2,113,536
    float* out_loss = ((size_t)out_size >= align_elems + BB) ? (out + align_elems)
                                                             : nullptr;

    unsigned short* wi;
    cudaGetSymbolAddress((void**)&wi, g_wi);

    const int gtotal = BB * TT * 65;
    gather_kernel<<<(gtotal + 255) / 256, 256>>>(logit, label, blankp);
    dp_kernel<<<BB, 32>>>(label, blankp, wi, out_loss);
    align_kernel<<<(BB * TT * 32 + 255) / 256, 256>>>(wi, out);
}